// round 3
// baseline (speedup 1.0000x reference)
#include <cuda_runtime.h>
#include <cuda_bf16.h>
#include <math.h>

// Problem dims (hardcoded from reference)
#define B_   256
#define IN_  1024
#define D_   512
#define P_   2048
#define SPLITK 8

// ---------------- scratch (device globals; no allocations allowed) ---------
__device__ float g_feat_part[SPLITK * B_ * D_];   // split-K partials for GEMM1
__device__ float g_feat[B_ * D_];                 // feat = x@Wb^T + bb
__device__ float g_feat_n2[B_];                   // per-row ||feat||^2
__device__ float g_prox_n2[P_];                   // per-row ||proxy||^2
__device__ float g_s[B_ * P_];                    // s = -den = 2*dot - fn2 - pn2
__device__ float g_row_val[B_];                   // logp[b, y[b]]

// ---------------- tiled NT GEMM core: C[m,n] = sum_k A[m,k]*B[n,k] ---------
#define BM 64
#define BN 64
#define BK 16

__device__ __forceinline__ void gemm_core_nt(
    const float* __restrict__ A, const float* __restrict__ Bm,
    int K, int m0, int n0, int k0, int k1, float acc[4][4])
{
    __shared__ float As[BK][BM + 4];
    __shared__ float Bs[BK][BN + 4];

    const int tid = threadIdx.x;
    const int tx  = tid & 15;        // 0..15 -> n fragment
    const int ty  = tid >> 4;        // 0..15 -> m fragment
    const int lr  = tid >> 2;        // 0..63 row within tile for loads
    const int lc  = (tid & 3) * 4;   // k offset 0,4,8,12

    const float* aptr = A + (size_t)(m0 + lr) * K + lc;
    const float* bptr = Bm + (size_t)(n0 + lr) * K + lc;

    for (int kt = k0; kt < k1; kt += BK) {
        float4 a4 = *(const float4*)(aptr + kt);
        float4 b4 = *(const float4*)(bptr + kt);
        __syncthreads();
        As[lc + 0][lr] = a4.x; As[lc + 1][lr] = a4.y;
        As[lc + 2][lr] = a4.z; As[lc + 3][lr] = a4.w;
        Bs[lc + 0][lr] = b4.x; Bs[lc + 1][lr] = b4.y;
        Bs[lc + 2][lr] = b4.z; Bs[lc + 3][lr] = b4.w;
        __syncthreads();
#pragma unroll
        for (int kk = 0; kk < BK; kk++) {
            float a[4], b[4];
#pragma unroll
            for (int i = 0; i < 4; i++) a[i] = As[kk][ty + 16 * i];
#pragma unroll
            for (int j = 0; j < 4; j++) b[j] = Bs[kk][tx + 16 * j];
#pragma unroll
            for (int i = 0; i < 4; i++)
#pragma unroll
                for (int j = 0; j < 4; j++)
                    acc[i][j] += a[i] * b[j];
        }
    }
}

// ---------------- GEMM1: feat partials (split-K) ---------------------------
__global__ __launch_bounds__(256, 2)
void gemm1_kernel(const float* __restrict__ x, const float* __restrict__ Wb)
{
    const int n0 = blockIdx.x * BN;      // over D_ (8 tiles)
    const int m0 = blockIdx.y * BM;      // over B_ (4 tiles)
    const int z  = blockIdx.z;           // split-K slice (8)
    const int kspan = IN_ / SPLITK;      // 128

    float acc[4][4] = {};
    gemm_core_nt(x, Wb, IN_, m0, n0, z * kspan, (z + 1) * kspan, acc);

    const int tx = threadIdx.x & 15, ty = threadIdx.x >> 4;
    float* dst = g_feat_part + (size_t)z * B_ * D_;
#pragma unroll
    for (int i = 0; i < 4; i++) {
        int m = m0 + ty + 16 * i;
#pragma unroll
        for (int j = 0; j < 4; j++) {
            int n = n0 + tx + 16 * j;
            dst[(size_t)m * D_ + n] = acc[i][j];
        }
    }
}

// ---------------- combine split-K + bias -----------------------------------
__global__ void combine_feat_kernel(const float* __restrict__ bb)
{
    int i = blockIdx.x * 256 + threadIdx.x;   // 131072 elems
    float s = bb[i & (D_ - 1)];
#pragma unroll
    for (int z = 0; z < SPLITK; z++) s += g_feat_part[(size_t)z * B_ * D_ + i];
    g_feat[i] = s;
}

// ---------------- per-row sum of squares (one warp per row) ----------------
// Device-symbol destinations referenced IN DEVICE CODE ONLY: passing a
// __device__ symbol as a host-side kernel arg passes the host shadow
// address (silent wrong-memory writes on GB300 due to ATS coherence).
__global__ void rowsumsq_feat_kernel()
{
    int row  = blockIdx.x * 8 + (threadIdx.x >> 5);
    int lane = threadIdx.x & 31;
    const float* r = g_feat + (size_t)row * D_;
    float s = 0.f;
    for (int j = lane; j < D_; j += 32) { float v = r[j]; s += v * v; }
#pragma unroll
    for (int o = 16; o; o >>= 1) s += __shfl_xor_sync(0xffffffff, s, o);
    if (lane == 0) g_feat_n2[row] = s;
}

__global__ void rowsumsq_prox_kernel(const float* __restrict__ proxies)
{
    int row  = blockIdx.x * 8 + (threadIdx.x >> 5);
    int lane = threadIdx.x & 31;
    const float* r = proxies + (size_t)row * D_;
    float s = 0.f;
    for (int j = lane; j < D_; j += 32) { float v = r[j]; s += v * v; }
#pragma unroll
    for (int o = 16; o; o >>= 1) s += __shfl_xor_sync(0xffffffff, s, o);
    if (lane == 0) g_prox_n2[row] = s;
}

// ---------------- fused GEMM2 (out) + GEMM3 (-den) -------------------------
__global__ __launch_bounds__(256, 2)
void gemm23_kernel(const float* __restrict__ Wm, const float* __restrict__ bm,
                   const float* __restrict__ proxies, float* __restrict__ out)
{
    const int nt = blockIdx.x;           // 0..63 ; <32 -> out head, >=32 -> proxies
    const int m0 = blockIdx.y * BM;
    const int tx = threadIdx.x & 15, ty = threadIdx.x >> 4;

    float acc[4][4] = {};
    if (nt < 32) {
        const int n0 = nt * BN;
        gemm_core_nt(g_feat, Wm, D_, m0, n0, 0, D_, acc);
#pragma unroll
        for (int i = 0; i < 4; i++) {
            int m = m0 + ty + 16 * i;
#pragma unroll
            for (int j = 0; j < 4; j++) {
                int n = n0 + tx + 16 * j;
                out[(size_t)m * P_ + n] = acc[i][j] + bm[n];
            }
        }
    } else {
        const int n0 = (nt - 32) * BN;
        gemm_core_nt(g_feat, proxies, D_, m0, n0, 0, D_, acc);
#pragma unroll
        for (int i = 0; i < 4; i++) {
            int m = m0 + ty + 16 * i;
            float fn2 = g_feat_n2[m];
#pragma unroll
            for (int j = 0; j < 4; j++) {
                int n = n0 + tx + 16 * j;
                g_s[(size_t)m * P_ + n] = 2.f * acc[i][j] - fn2 - g_prox_n2[n];
            }
        }
    }
}

// ---------------- per-row log-softmax CE term ------------------------------
__global__ void loss_kernel(const int* __restrict__ y)
{
    const int b = blockIdx.x;
    const int t = threadIdx.x;
    const float* row = g_s + (size_t)b * P_;
    __shared__ float red[256];

    float mx = -INFINITY;
    for (int j = t; j < P_; j += 256) mx = fmaxf(mx, row[j]);
    red[t] = mx; __syncthreads();
    for (int st = 128; st > 0; st >>= 1) {
        if (t < st) red[t] = fmaxf(red[t], red[t + st]);
        __syncthreads();
    }
    mx = red[0]; __syncthreads();

    float sum = 0.f;
    for (int j = t; j < P_; j += 256) sum += expf(row[j] - mx);
    red[t] = sum; __syncthreads();
    for (int st = 128; st > 0; st >>= 1) {
        if (t < st) red[t] += red[t + st];
        __syncthreads();
    }
    if (t == 0) g_row_val[b] = row[y[b]] - mx - logf(red[0]);
}

// ---------------- final scalars --------------------------------------------
__global__ void final_kernel(float* __restrict__ out)
{
    __shared__ float r1[256], r2[256];
    int t = threadIdx.x;
    r1[t] = g_row_val[t];
    r2[t] = sqrtf(g_feat_n2[t]);
    __syncthreads();
    for (int st = 128; st > 0; st >>= 1) {
        if (t < st) { r1[t] += r1[t + st]; r2[t] += r2[t + st]; }
        __syncthreads();
    }
    if (t == 0) {
        out[(size_t)B_ * P_]     = -r1[0] / (float)B_;  // loss
        out[(size_t)B_ * P_ + 1] =  r2[0] / (float)B_;  // reg_e
    }
}

// ---------------- launch ----------------------------------------------------
extern "C" void kernel_launch(void* const* d_in, const int* in_sizes, int n_in,
                              void* d_out, int out_size)
{
    const float* x       = (const float*)d_in[0];
    const int*   y       = (const int*)  d_in[1];
    const float* Wb      = (const float*)d_in[2];
    const float* bb      = (const float*)d_in[3];
    const float* Wm      = (const float*)d_in[4];
    const float* bm      = (const float*)d_in[5];
    const float* proxies = (const float*)d_in[6];
    float* out = (float*)d_out;

    // 1) feat partials: grid (Ntiles=8, Mtiles=4, splitK=8) = 256 blocks
    gemm1_kernel<<<dim3(D_ / BN, B_ / BM, SPLITK), 256>>>(x, Wb);
    // 2) reduce partials + bias
    combine_feat_kernel<<<(B_ * D_) / 256, 256>>>(bb);
    // 3) norms (device-symbol destinations, referenced in device code)
    rowsumsq_feat_kernel<<<B_ / 8, 256>>>();
    rowsumsq_prox_kernel<<<P_ / 8, 256>>>(proxies);
    // 4) fused out-head + (-den): grid (64, 4) = 256 blocks
    gemm23_kernel<<<dim3(2 * P_ / BN, B_ / BM), 256>>>(Wm, bm, proxies, out);
    // 5) per-row CE
    loss_kernel<<<B_, 256>>>(y);
    // 6) scalars
    final_kernel<<<1, 256>>>(out);
}

// round 5
// speedup vs baseline: 1.7327x; 1.7327x over previous
#include <cuda_runtime.h>
#include <cuda_bf16.h>
#include <math.h>
#include <stdint.h>

#define B_   256
#define IN_  1024
#define D_   512
#define P_   2048
#define SPLITK 4

// ---------------- scratch (device globals; no allocations allowed) ---------
__device__ float g_feat_part[SPLITK * B_ * D_];   // split-K partials for GEMM1
__device__ float g_feat[B_ * D_];                 // feat = x@Wb^T + bb
__device__ float g_feat_n2[B_];                   // per-row ||feat||^2
__device__ float g_s[B_ * P_];                    // s = -den = 2*dot - fn2 - pn2
__device__ float g_row_val[B_];                   // logp[b, y[b]]

// ==================== tf32 mma.sync helpers ================================
// m16n8k8 row.col: D(16x8,f32) += A(16x8,tf32) * B(8x8,tf32 col-major = [n][k])
__device__ __forceinline__ void mma_tf32(float c[4], const uint32_t a[4], const uint32_t b[2]) {
    asm volatile("mma.sync.aligned.m16n8k8.row.col.f32.tf32.tf32.f32 "
        "{%0,%1,%2,%3}, {%4,%5,%6,%7}, {%8,%9}, {%0,%1,%2,%3};"
        : "+f"(c[0]), "+f"(c[1]), "+f"(c[2]), "+f"(c[3])
        : "r"(a[0]), "r"(a[1]), "r"(a[2]), "r"(a[3]), "r"(b[0]), "r"(b[1]));
}

// fp32 -> tf32 round-to-nearest (avoids truncation bias of raw HW conversion)
__device__ __forceinline__ float to_tf32(float x) {
    uint32_t r;
    asm("cvt.rna.tf32.f32 %0, %1;" : "=r"(r) : "f"(x));
    return __uint_as_float(r);
}

// SMEM tile layout ("pair-interleaved"): per row of Kc=32 floats, pair index
// p = j*4 + t (j = k8 block 0..3, t = 0..3) holds float2 {X[j*8+t], X[j*8+t+4]}.
// Row stride = 160 bytes (20 float2). Fragment LDS.64 banks = 8r + 2t mod 32:
// all 16 lanes of a phase hit distinct banks -> conflict-free.
#define RS_BYTES 160
#define RS_F2    20

// global -> regs: one task = (row, j); loads 2x float4 covering k8 block j
template<int ROWS>
__device__ __forceinline__ void pack_load(const float* __restrict__ src, int ldk,
        int row0, int kt, int tid, float4* v0, float4* v1)
{
    constexpr int T = (ROWS * 4) / 256;
#pragma unroll
    for (int it = 0; it < T; it++) {
        int task = it * 256 + tid;
        int r = task >> 2, j = task & 3;
        const float* p = src + (size_t)(row0 + r) * ldk + kt + j * 8;
        v0[it] = *(const float4*)p;
        v1[it] = *(const float4*)(p + 4);
    }
}

// regs -> smem (tf32-converted, pair-interleaved); accumulates fp32 sumsq
template<int ROWS>
__device__ __forceinline__ void pack_store(char* __restrict__ buf, int tid,
        const float4* v0, const float4* v1, float* sq)
{
    constexpr int T = (ROWS * 4) / 256;
#pragma unroll
    for (int it = 0; it < T; it++) {
        int task = it * 256 + tid;
        int r = task >> 2, j = task & 3;
        float4 a = v0[it], b = v1[it];
        sq[it] += a.x * a.x + a.y * a.y + a.z * a.z + a.w * a.w
                + b.x * b.x + b.y * b.y + b.z * b.z + b.w * b.w;
        float4 w0 = make_float4(to_tf32(a.x), to_tf32(b.x), to_tf32(a.y), to_tf32(b.y));
        float4 w1 = make_float4(to_tf32(a.z), to_tf32(b.z), to_tf32(a.w), to_tf32(b.w));
        float4* dst = (float4*)(buf + r * RS_BYTES + j * 32);
        dst[0] = w0;
        dst[1] = w1;
    }
}

// one Kc=32 chunk of warp-level mma from packed smem tiles
template<int WN8>
__device__ __forceinline__ void chunk_mma(const float2* __restrict__ As,
        const float2* __restrict__ Bs, int wm32, int wnb, int g, int t,
        float acc[2][WN8][4])
{
#pragma unroll
    for (int j = 0; j < 4; j++) {
        uint32_t af[2][4];
#pragma unroll
        for (int i = 0; i < 2; i++) {
            float2 p0 = As[(wm32 + i * 16 + g) * RS_F2 + j * 4 + t];
            float2 p1 = As[(wm32 + i * 16 + 8 + g) * RS_F2 + j * 4 + t];
            af[i][0] = __float_as_uint(p0.x);   // (g,   t)
            af[i][1] = __float_as_uint(p1.x);   // (g+8, t)
            af[i][2] = __float_as_uint(p0.y);   // (g,   t+4)
            af[i][3] = __float_as_uint(p1.y);   // (g+8, t+4)
        }
        uint32_t bf[WN8][2];
#pragma unroll
        for (int nn = 0; nn < WN8; nn++) {
            float2 pb = Bs[(wnb + nn * 8 + g) * RS_F2 + j * 4 + t];
            bf[nn][0] = __float_as_uint(pb.x);  // (k=t,   n=g)
            bf[nn][1] = __float_as_uint(pb.y);  // (k=t+4, n=g)
        }
#pragma unroll
        for (int i = 0; i < 2; i++)
#pragma unroll
            for (int nn = 0; nn < WN8; nn++)
                mma_tf32(acc[i][nn], af[i], bf[nn]);
    }
}

// ---------------- GEMM1: split-K partials of x @ Wb^T (64x64 tiles) --------
__global__ __launch_bounds__(256, 1)
void gemm1_mma(const float* __restrict__ x, const float* __restrict__ Wb)
{
    extern __shared__ __align__(16) char smem[];
    constexpr int TB = 64 * RS_BYTES;                 // 10240
    char* As[2] = { smem,          smem + 2 * TB };
    char* Bs[2] = { smem + TB,     smem + 3 * TB };

    const int tid = threadIdx.x, wid = tid >> 5, lane = tid & 31;
    const int g = lane >> 2, t = lane & 3;
    const int n0 = blockIdx.x * 64;                   // over D_
    const int m0 = blockIdx.y * 64;                   // over B_
    const int z  = blockIdx.z;
    const int kb = z * (IN_ / SPLITK);                // 256-wide K slice
    const int wm32 = (wid & 1) * 32, wnb = (wid >> 1) * 16;

    float acc[2][2][4] = {};
    float4 a0[1], a1[1], b0[1], b1[1];
    float sqA[1] = {0.f}, sqB[1] = {0.f};

    pack_load<64>(x,  IN_, m0, kb, tid, a0, a1);
    pack_load<64>(Wb, IN_, n0, kb, tid, b0, b1);
    pack_store<64>(As[0], tid, a0, a1, sqA);
    pack_store<64>(Bs[0], tid, b0, b1, sqB);
    __syncthreads();
    constexpr int NCH = (IN_ / SPLITK) / 32;          // 8
    for (int c = 0; c < NCH; c++) {
        if (c + 1 < NCH) {
            pack_load<64>(x,  IN_, m0, kb + (c + 1) * 32, tid, a0, a1);
            pack_load<64>(Wb, IN_, n0, kb + (c + 1) * 32, tid, b0, b1);
        }
        chunk_mma<2>((const float2*)As[c & 1], (const float2*)Bs[c & 1],
                     wm32, wnb, g, t, acc);
        if (c + 1 < NCH) {
            pack_store<64>(As[(c + 1) & 1], tid, a0, a1, sqA);
            pack_store<64>(Bs[(c + 1) & 1], tid, b0, b1, sqB);
            __syncthreads();
        }
    }

    float* dst = g_feat_part + (size_t)z * B_ * D_;
#pragma unroll
    for (int i = 0; i < 2; i++) {
        int m = m0 + wm32 + i * 16 + g;
#pragma unroll
        for (int nn = 0; nn < 2; nn++) {
            int n = n0 + wnb + nn * 8 + 2 * t;
            *(float2*)(dst + (size_t)m * D_ + n) =
                make_float2(acc[i][nn][0], acc[i][nn][1]);
            *(float2*)(dst + (size_t)(m + 8) * D_ + n) =
                make_float2(acc[i][nn][2], acc[i][nn][3]);
        }
    }
}

// ---------------- combine split-K + bias -----------------------------------
__global__ void combine_feat_kernel(const float* __restrict__ bb)
{
    int i = blockIdx.x * 256 + threadIdx.x;
    float s = bb[i & (D_ - 1)];
#pragma unroll
    for (int z = 0; z < SPLITK; z++) s += g_feat_part[(size_t)z * B_ * D_ + i];
    g_feat[i] = s;
}

// ---------------- fused GEMM2 (out) + GEMM3 (-den), 128x128x512 ------------
__global__ __launch_bounds__(256, 1)
void gemm23_mma(const float* __restrict__ Wm, const float* __restrict__ bm,
                const float* __restrict__ proxies, float* __restrict__ out)
{
    extern __shared__ __align__(16) char smem[];
    constexpr int TB = 128 * RS_BYTES;                // 20480
    char* As[2] = { smem,          smem + 2 * TB };
    char* Bs[2] = { smem + TB,     smem + 3 * TB };
    float* fn2s = (float*)(smem + 4 * TB);            // [128]
    float* pn2s = fn2s + 128;                         // [128]

    const int tid = threadIdx.x, wid = tid >> 5, lane = tid & 31;
    const int g = lane >> 2, t = lane & 3;
    const int nt = blockIdx.x;                        // 0..31
    const bool isp = (nt >= 16);
    const int n0 = (isp ? nt - 16 : nt) * 128;
    const int m0 = blockIdx.y * 128;
    const float* Bmat = isp ? proxies : Wm;
    const int wm32 = (wid & 3) * 32, wnb = (wid >> 2) * 64;

    float acc[2][8][4] = {};
    float4 a0[2], a1[2], b0[2], b1[2];
    float sqA[2] = {0.f, 0.f}, sqB[2] = {0.f, 0.f};

    pack_load<128>(g_feat, D_, m0, 0, tid, a0, a1);
    pack_load<128>(Bmat,  D_, n0, 0, tid, b0, b1);
    pack_store<128>(As[0], tid, a0, a1, sqA);
    pack_store<128>(Bs[0], tid, b0, b1, sqB);
    __syncthreads();
    constexpr int NCH = D_ / 32;                      // 16
    for (int c = 0; c < NCH; c++) {
        if (c + 1 < NCH) {
            pack_load<128>(g_feat, D_, m0, (c + 1) * 32, tid, a0, a1);
            pack_load<128>(Bmat,  D_, n0, (c + 1) * 32, tid, b0, b1);
        }
        chunk_mma<8>((const float2*)As[c & 1], (const float2*)Bs[c & 1],
                     wm32, wnb, g, t, acc);
        if (c + 1 < NCH) {
            pack_store<128>(As[(c + 1) & 1], tid, a0, a1, sqA);
            pack_store<128>(Bs[(c + 1) & 1], tid, b0, b1, sqB);
            __syncthreads();
        }
    }

    // per-row sumsq: reduce across the 4 j-threads of each row (quad shuffle)
#pragma unroll
    for (int it = 0; it < 2; it++) {
        float sa = sqA[it], sb = sqB[it];
        sa += __shfl_xor_sync(0xffffffffu, sa, 1);
        sa += __shfl_xor_sync(0xffffffffu, sa, 2);
        sb += __shfl_xor_sync(0xffffffffu, sb, 1);
        sb += __shfl_xor_sync(0xffffffffu, sb, 2);
        int r = (it * 256 + tid) >> 2;
        if ((tid & 3) == 0) { fn2s[r] = sa; pn2s[r] = sb; }
    }
    __syncthreads();

    if (nt == 16 && tid < 128) g_feat_n2[m0 + tid] = fn2s[tid];  // for reg_e

#pragma unroll
    for (int i = 0; i < 2; i++) {
        int ml = wm32 + i * 16 + g;                   // local row (and +8)
        int m  = m0 + ml;
        if (!isp) {
#pragma unroll
            for (int nn = 0; nn < 8; nn++) {
                int n = n0 + wnb + nn * 8 + 2 * t;
                float bn0 = bm[n], bn1 = bm[n + 1];
                *(float2*)(out + (size_t)m * P_ + n) =
                    make_float2(acc[i][nn][0] + bn0, acc[i][nn][1] + bn1);
                *(float2*)(out + (size_t)(m + 8) * P_ + n) =
                    make_float2(acc[i][nn][2] + bn0, acc[i][nn][3] + bn1);
            }
        } else {
            float fa = fn2s[ml], fb = fn2s[ml + 8];
#pragma unroll
            for (int nn = 0; nn < 8; nn++) {
                int nl = wnb + nn * 8 + 2 * t;
                int n  = n0 + nl;
                float pa = pn2s[nl], pb = pn2s[nl + 1];
                *(float2*)(g_s + (size_t)m * P_ + n) =
                    make_float2(2.f * acc[i][nn][0] - fa - pa,
                                2.f * acc[i][nn][1] - fa - pb);
                *(float2*)(g_s + (size_t)(m + 8) * P_ + n) =
                    make_float2(2.f * acc[i][nn][2] - fb - pa,
                                2.f * acc[i][nn][3] - fb - pb);
            }
        }
    }
}

// ---------------- per-row log-softmax CE term (single pass, regs) ----------
__global__ void loss_kernel(const int* __restrict__ y)
{
    const int b = blockIdx.x, t = threadIdx.x;
    const float4* row4 = (const float4*)(g_s + (size_t)b * P_);
    const float4 v0 = row4[t], v1 = row4[t + 256];
    __shared__ float red[256];

    float mx = fmaxf(fmaxf(fmaxf(v0.x, v0.y), fmaxf(v0.z, v0.w)),
                     fmaxf(fmaxf(v1.x, v1.y), fmaxf(v1.z, v1.w)));
    red[t] = mx; __syncthreads();
    for (int st = 128; st > 0; st >>= 1) {
        if (t < st) red[t] = fmaxf(red[t], red[t + st]);
        __syncthreads();
    }
    mx = red[0]; __syncthreads();

    float s = expf(v0.x - mx) + expf(v0.y - mx) + expf(v0.z - mx) + expf(v0.w - mx)
            + expf(v1.x - mx) + expf(v1.y - mx) + expf(v1.z - mx) + expf(v1.w - mx);
    red[t] = s; __syncthreads();
    for (int st = 128; st > 0; st >>= 1) {
        if (t < st) red[t] += red[t + st];
        __syncthreads();
    }
    if (t == 0) g_row_val[b] = g_s[(size_t)b * P_ + y[b]] - mx - logf(red[0]);
}

// ---------------- final scalars --------------------------------------------
__global__ void final_kernel(float* __restrict__ out)
{
    __shared__ float r1[256], r2[256];
    const int t = threadIdx.x;
    r1[t] = g_row_val[t];
    r2[t] = sqrtf(g_feat_n2[t]);
    __syncthreads();
    for (int st = 128; st > 0; st >>= 1) {
        if (t < st) { r1[t] += r1[t + st]; r2[t] += r2[t + st]; }
        __syncthreads();
    }
    if (t == 0) {
        out[(size_t)B_ * P_]     = -r1[0] / (float)B_;  // loss
        out[(size_t)B_ * P_ + 1] =  r2[0] / (float)B_;  // reg_e
    }
}

// ---------------- launch ----------------------------------------------------
extern "C" void kernel_launch(void* const* d_in, const int* in_sizes, int n_in,
                              void* d_out, int out_size)
{
    const float* x       = (const float*)d_in[0];
    const int*   y       = (const int*)  d_in[1];
    const float* Wb      = (const float*)d_in[2];
    const float* bb      = (const float*)d_in[3];
    const float* Wm      = (const float*)d_in[4];
    const float* bm      = (const float*)d_in[5];
    const float* proxies = (const float*)d_in[6];
    float* out = (float*)d_out;

    const int SMEM1 = 4 * 64  * RS_BYTES;             // 40960
    const int SMEM2 = 4 * 128 * RS_BYTES + 1024;      // 82944 (tiles + n2 arrays)
    cudaFuncSetAttribute(gemm1_mma,  cudaFuncAttributeMaxDynamicSharedMemorySize, SMEM1);
    cudaFuncSetAttribute(gemm23_mma, cudaFuncAttributeMaxDynamicSharedMemorySize, SMEM2);

    // 1) feat partials: (D/64, B/64, splitK) = 128 CTAs
    gemm1_mma<<<dim3(D_ / 64, B_ / 64, SPLITK), 256, SMEM1>>>(x, Wb);
    // 2) combine + bias
    combine_feat_kernel<<<(B_ * D_) / 256, 256>>>(bb);
    // 3) fused out-head + (-den): (32, 2) = 64 CTAs; also emits fn2/pn2
    gemm23_mma<<<dim3(2 * (P_ / 128), B_ / 128), 256, SMEM2>>>(Wm, bm, proxies, out);
    // 4) per-row CE
    loss_kernel<<<B_, 256>>>(y);
    // 5) scalars
    final_kernel<<<1, 256>>>(out);
}

// round 6
// speedup vs baseline: 1.8501x; 1.0678x over previous
#include <cuda_runtime.h>
#include <cuda_bf16.h>
#include <math.h>
#include <stdint.h>

#define B_   256
#define IN_  1024
#define D_   512
#define P_   2048
#define SPLITK 4
#define NT_P  (P_ / 64)     // 32 proxy n-tiles per row

// ---------------- scratch (device globals; no allocations allowed) ---------
__device__ float g_feat_part[SPLITK * B_ * D_];   // split-K partials for GEMM1
__device__ float g_feat[B_ * D_];                 // feat = x@Wb^T + bb
__device__ float g_feat_n2[B_];                   // per-row ||feat||^2
__device__ float g_pmax[B_ * NT_P];               // per (row, n-tile) partial max of s
__device__ float g_psum[B_ * NT_P];               // per (row, n-tile) partial sumexp
__device__ float g_sy[B_];                        // s[b, y[b]]

// ==================== tf32 mma.sync helpers ================================
__device__ __forceinline__ void mma_tf32(float c[4], const uint32_t a[4], const uint32_t b[2]) {
    asm volatile("mma.sync.aligned.m16n8k8.row.col.f32.tf32.tf32.f32 "
        "{%0,%1,%2,%3}, {%4,%5,%6,%7}, {%8,%9}, {%0,%1,%2,%3};"
        : "+f"(c[0]), "+f"(c[1]), "+f"(c[2]), "+f"(c[3])
        : "r"(a[0]), "r"(a[1]), "r"(a[2]), "r"(a[3]), "r"(b[0]), "r"(b[1]));
}

__device__ __forceinline__ float to_tf32(float x) {
    uint32_t r;
    asm("cvt.rna.tf32.f32 %0, %1;" : "=r"(r) : "f"(x));
    return __uint_as_float(r);
}

// SMEM tile layout ("pair-interleaved"): per row of Kc=32 floats, pair index
// p = j*4 + t holds float2 {X[j*8+t], X[j*8+t+4]}. Row stride 160B: LDS.64
// fragment fetches are conflict-free (banks 8r+2t all distinct per phase).
#define RS_BYTES 160
#define RS_F2    20

template<int ROWS>
__device__ __forceinline__ void pack_load(const float* __restrict__ src, int ldk,
        int row0, int kt, int tid, float4* v0, float4* v1)
{
    constexpr int T = (ROWS * 4) / 256;
#pragma unroll
    for (int it = 0; it < T; it++) {
        int task = it * 256 + tid;
        int r = task >> 2, j = task & 3;
        const float* p = src + (size_t)(row0 + r) * ldk + kt + j * 8;
        v0[it] = *(const float4*)p;
        v1[it] = *(const float4*)(p + 4);
    }
}

template<int ROWS>
__device__ __forceinline__ void pack_store(char* __restrict__ buf, int tid,
        const float4* v0, const float4* v1, float* sq)
{
    constexpr int T = (ROWS * 4) / 256;
#pragma unroll
    for (int it = 0; it < T; it++) {
        int task = it * 256 + tid;
        int r = task >> 2, j = task & 3;
        float4 a = v0[it], b = v1[it];
        sq[it] += a.x * a.x + a.y * a.y + a.z * a.z + a.w * a.w
                + b.x * b.x + b.y * b.y + b.z * b.z + b.w * b.w;
        float4 w0 = make_float4(to_tf32(a.x), to_tf32(b.x), to_tf32(a.y), to_tf32(b.y));
        float4 w1 = make_float4(to_tf32(a.z), to_tf32(b.z), to_tf32(a.w), to_tf32(b.w));
        float4* dst = (float4*)(buf + r * RS_BYTES + j * 32);
        dst[0] = w0;
        dst[1] = w1;
    }
}

template<int WN8>
__device__ __forceinline__ void chunk_mma(const float2* __restrict__ As,
        const float2* __restrict__ Bs, int wm32, int wnb, int g, int t,
        float acc[2][WN8][4])
{
#pragma unroll
    for (int j = 0; j < 4; j++) {
        uint32_t af[2][4];
#pragma unroll
        for (int i = 0; i < 2; i++) {
            float2 p0 = As[(wm32 + i * 16 + g) * RS_F2 + j * 4 + t];
            float2 p1 = As[(wm32 + i * 16 + 8 + g) * RS_F2 + j * 4 + t];
            af[i][0] = __float_as_uint(p0.x);
            af[i][1] = __float_as_uint(p1.x);
            af[i][2] = __float_as_uint(p0.y);
            af[i][3] = __float_as_uint(p1.y);
        }
        uint32_t bf[WN8][2];
#pragma unroll
        for (int nn = 0; nn < WN8; nn++) {
            float2 pb = Bs[(wnb + nn * 8 + g) * RS_F2 + j * 4 + t];
            bf[nn][0] = __float_as_uint(pb.x);
            bf[nn][1] = __float_as_uint(pb.y);
        }
#pragma unroll
        for (int i = 0; i < 2; i++)
#pragma unroll
            for (int nn = 0; nn < WN8; nn++)
                mma_tf32(acc[i][nn], af[i], bf[nn]);
    }
}

// ---------------- GEMM1: split-K partials of x @ Wb^T (64x64 tiles) --------
__global__ __launch_bounds__(256, 1)
void gemm1_mma(const float* __restrict__ x, const float* __restrict__ Wb)
{
    extern __shared__ __align__(16) char smem[];
    constexpr int TB = 64 * RS_BYTES;                 // 10240
    char* As[2] = { smem,          smem + 2 * TB };
    char* Bs[2] = { smem + TB,     smem + 3 * TB };

    const int tid = threadIdx.x, wid = tid >> 5, lane = tid & 31;
    const int g = lane >> 2, t = lane & 3;
    const int n0 = blockIdx.x * 64;
    const int m0 = blockIdx.y * 64;
    const int z  = blockIdx.z;
    const int kb = z * (IN_ / SPLITK);
    const int wm32 = (wid & 1) * 32, wnb = (wid >> 1) * 16;

    float acc[2][2][4] = {};
    float4 a0[1], a1[1], b0[1], b1[1];
    float sq[1] = {0.f};

    pack_load<64>(x,  IN_, m0, kb, tid, a0, a1);
    pack_load<64>(Wb, IN_, n0, kb, tid, b0, b1);
    pack_store<64>(As[0], tid, a0, a1, sq);
    pack_store<64>(Bs[0], tid, b0, b1, sq);
    __syncthreads();
    constexpr int NCH = (IN_ / SPLITK) / 32;          // 8
    for (int c = 0; c < NCH; c++) {
        if (c + 1 < NCH) {
            pack_load<64>(x,  IN_, m0, kb + (c + 1) * 32, tid, a0, a1);
            pack_load<64>(Wb, IN_, n0, kb + (c + 1) * 32, tid, b0, b1);
        }
        chunk_mma<2>((const float2*)As[c & 1], (const float2*)Bs[c & 1],
                     wm32, wnb, g, t, acc);
        if (c + 1 < NCH) {
            pack_store<64>(As[(c + 1) & 1], tid, a0, a1, sq);
            pack_store<64>(Bs[(c + 1) & 1], tid, b0, b1, sq);
            __syncthreads();
        }
    }

    float* dst = g_feat_part + (size_t)z * B_ * D_;
#pragma unroll
    for (int i = 0; i < 2; i++) {
        int m = m0 + wm32 + i * 16 + g;
#pragma unroll
        for (int nn = 0; nn < 2; nn++) {
            int n = n0 + wnb + nn * 8 + 2 * t;
            *(float2*)(dst + (size_t)m * D_ + n) =
                make_float2(acc[i][nn][0], acc[i][nn][1]);
            *(float2*)(dst + (size_t)(m + 8) * D_ + n) =
                make_float2(acc[i][nn][2], acc[i][nn][3]);
        }
    }
}

// ---------------- combine split-K + bias -----------------------------------
__global__ void combine_feat_kernel(const float* __restrict__ bb)
{
    int i = blockIdx.x * 256 + threadIdx.x;
    float s = bb[i & (D_ - 1)];
#pragma unroll
    for (int z = 0; z < SPLITK; z++) s += g_feat_part[(size_t)z * B_ * D_ + i];
    g_feat[i] = s;
}

// ---------------- fused GEMM2 (out) + GEMM3 (softmax partials) -------------
// Tiles 128(m) x 64(n), K=512. grid (64, 2) = 128 CTAs.
// nt<32: out-head (writes out + bm). nt>=32: proxy tile — computes
// s = 2*dot - fn2 - pn2 in regs, reduces per-row (max, sumexp) partials,
// extracts s[b, y[b]]. g_s never materialized.
__global__ __launch_bounds__(256, 1)
void gemm23_mma(const float* __restrict__ Wm, const float* __restrict__ bm,
                const float* __restrict__ proxies, const int* __restrict__ y,
                float* __restrict__ out)
{
    extern __shared__ __align__(16) char smem[];
    constexpr int TBA = 128 * RS_BYTES;               // 20480
    constexpr int TBB = 64 * RS_BYTES;                // 10240
    char* As[2] = { smem,                smem + TBA + TBB };
    char* Bs[2] = { smem + TBA,          smem + 2 * TBA + TBB };
    float* fn2s = (float*)(smem + 2 * (TBA + TBB));   // [128]
    float* pn2s = fn2s + 128;                         // [64]
    float* pmx  = pn2s + 64;                          // [128][2]
    float* psm  = pmx + 256;                          // [128][2]

    const int tid = threadIdx.x, wid = tid >> 5, lane = tid & 31;
    const int g = lane >> 2, t = lane & 3;
    const int nt = blockIdx.x;                        // 0..63
    const bool isp = (nt >= 32);
    const int n0 = (nt & 31) * 64;
    const int m0 = blockIdx.y * 128;
    const float* Bmat = isp ? proxies : Wm;
    const int wm32 = (wid & 3) * 32, wnb = (wid >> 2) * 32;
    const int half = wid >> 2;

    float acc[2][4][4] = {};
    float4 a0[2], a1[2], b0[1], b1[1];
    float sqA[2] = {0.f, 0.f}, sqB[1] = {0.f};

    pack_load<128>(g_feat, D_, m0, 0, tid, a0, a1);
    pack_load<64>(Bmat,   D_, n0, 0, tid, b0, b1);
    pack_store<128>(As[0], tid, a0, a1, sqA);
    pack_store<64>(Bs[0], tid, b0, b1, sqB);
    __syncthreads();
    constexpr int NCH = D_ / 32;                      // 16
    for (int c = 0; c < NCH; c++) {
        if (c + 1 < NCH) {
            pack_load<128>(g_feat, D_, m0, (c + 1) * 32, tid, a0, a1);
            pack_load<64>(Bmat,   D_, n0, (c + 1) * 32, tid, b0, b1);
        }
        chunk_mma<4>((const float2*)As[c & 1], (const float2*)Bs[c & 1],
                     wm32, wnb, g, t, acc);
        if (c + 1 < NCH) {
            pack_store<128>(As[(c + 1) & 1], tid, a0, a1, sqA);
            pack_store<64>(Bs[(c + 1) & 1], tid, b0, b1, sqB);
            __syncthreads();
        }
    }

    // per-row sumsq (fp32, over full K): quad-shuffle reduce, publish to smem
#pragma unroll
    for (int it = 0; it < 2; it++) {
        float sa = sqA[it];
        sa += __shfl_xor_sync(0xffffffffu, sa, 1);
        sa += __shfl_xor_sync(0xffffffffu, sa, 2);
        if ((tid & 3) == 0) fn2s[(it * 256 + tid) >> 2] = sa;
    }
    {
        float sb = sqB[0];
        sb += __shfl_xor_sync(0xffffffffu, sb, 1);
        sb += __shfl_xor_sync(0xffffffffu, sb, 2);
        if ((tid & 3) == 0) pn2s[tid >> 2] = sb;
    }
    __syncthreads();

    if (isp && (nt == 32) && tid < 128) g_feat_n2[m0 + tid] = fn2s[tid];

    if (!isp) {
#pragma unroll
        for (int i = 0; i < 2; i++) {
            int m = m0 + wm32 + i * 16 + g;
#pragma unroll
            for (int nn = 0; nn < 4; nn++) {
                int n = n0 + wnb + nn * 8 + 2 * t;
                float bn0 = bm[n], bn1 = bm[n + 1];
                *(float2*)(out + (size_t)m * P_ + n) =
                    make_float2(acc[i][nn][0] + bn0, acc[i][nn][1] + bn1);
                *(float2*)(out + (size_t)(m + 8) * P_ + n) =
                    make_float2(acc[i][nn][2] + bn0, acc[i][nn][3] + bn1);
            }
        }
    } else {
        // proxy: s values in regs -> per-row partial (max, sumexp) + y-pick
#pragma unroll
        for (int i = 0; i < 2; i++) {
            const int rA = wm32 + i * 16 + g;         // local rows rA, rA+8
            const int rB = rA + 8;
            const float fa = fn2s[rA], fb = fn2s[rB];
            const int ya = y[m0 + rA], yb = y[m0 + rB];
            float sA[8], sB[8];
#pragma unroll
            for (int nn = 0; nn < 4; nn++) {
                int nl = wnb + nn * 8 + 2 * t;
                float p0 = pn2s[nl], p1 = pn2s[nl + 1];
                sA[nn * 2 + 0] = 2.f * acc[i][nn][0] - fa - p0;
                sA[nn * 2 + 1] = 2.f * acc[i][nn][1] - fa - p1;
                sB[nn * 2 + 0] = 2.f * acc[i][nn][2] - fb - p0;
                sB[nn * 2 + 1] = 2.f * acc[i][nn][3] - fb - p1;
                int n = n0 + nl;
                if (n     == ya) g_sy[m0 + rA] = sA[nn * 2 + 0];
                if (n + 1 == ya) g_sy[m0 + rA] = sA[nn * 2 + 1];
                if (n     == yb) g_sy[m0 + rB] = sB[nn * 2 + 0];
                if (n + 1 == yb) g_sy[m0 + rB] = sB[nn * 2 + 1];
            }
            float mA = sA[0], mB = sB[0];
#pragma unroll
            for (int u = 1; u < 8; u++) { mA = fmaxf(mA, sA[u]); mB = fmaxf(mB, sB[u]); }
            float eA = 0.f, eB = 0.f;
#pragma unroll
            for (int u = 0; u < 8; u++) { eA += expf(sA[u] - mA); eB += expf(sB[u] - mB); }
            // quad reduce (max, sum) across t=0..3
#pragma unroll
            for (int o = 1; o <= 2; o <<= 1) {
                float mA2 = __shfl_xor_sync(0xffffffffu, mA, o);
                float eA2 = __shfl_xor_sync(0xffffffffu, eA, o);
                float mB2 = __shfl_xor_sync(0xffffffffu, mB, o);
                float eB2 = __shfl_xor_sync(0xffffffffu, eB, o);
                float M = fmaxf(mA, mA2);
                eA = eA * expf(mA - M) + eA2 * expf(mA2 - M); mA = M;
                M = fmaxf(mB, mB2);
                eB = eB * expf(mB - M) + eB2 * expf(mB2 - M); mB = M;
            }
            if (t == 0) {
                pmx[rA * 2 + half] = mA; psm[rA * 2 + half] = eA;
                pmx[rB * 2 + half] = mB; psm[rB * 2 + half] = eB;
            }
        }
        __syncthreads();
        if (tid < 128) {
            float m1 = pmx[tid * 2], m2 = pmx[tid * 2 + 1];
            float M = fmaxf(m1, m2);
            float S = psm[tid * 2] * expf(m1 - M) + psm[tid * 2 + 1] * expf(m2 - M);
            int idx = (m0 + tid) * NT_P + (nt - 32);
            g_pmax[idx] = M;
            g_psum[idx] = S;
        }
    }
}

// ---------------- final: logsumexp combine + both scalar means -------------
__global__ void final_kernel(float* __restrict__ out)
{
    __shared__ float r1[256], r2[256];
    const int b = threadIdx.x;                        // one row per thread
    float M = -INFINITY;
#pragma unroll
    for (int i = 0; i < NT_P; i++) M = fmaxf(M, g_pmax[b * NT_P + i]);
    float S = 0.f;
#pragma unroll
    for (int i = 0; i < NT_P; i++)
        S += g_psum[b * NT_P + i] * expf(g_pmax[b * NT_P + i] - M);
    r1[b] = g_sy[b] - M - logf(S);                    // logp[b, y[b]]
    r2[b] = sqrtf(g_feat_n2[b]);
    __syncthreads();
    for (int st = 128; st > 0; st >>= 1) {
        if (b < st) { r1[b] += r1[b + st]; r2[b] += r2[b + st]; }
        __syncthreads();
    }
    if (b == 0) {
        out[(size_t)B_ * P_]     = -r1[0] / (float)B_;  // loss
        out[(size_t)B_ * P_ + 1] =  r2[0] / (float)B_;  // reg_e
    }
}

// ---------------- launch ----------------------------------------------------
extern "C" void kernel_launch(void* const* d_in, const int* in_sizes, int n_in,
                              void* d_out, int out_size)
{
    const float* x       = (const float*)d_in[0];
    const int*   y       = (const int*)  d_in[1];
    const float* Wb      = (const float*)d_in[2];
    const float* bb      = (const float*)d_in[3];
    const float* Wm      = (const float*)d_in[4];
    const float* bm      = (const float*)d_in[5];
    const float* proxies = (const float*)d_in[6];
    float* out = (float*)d_out;

    const int SMEM1 = 4 * 64 * RS_BYTES;                       // 40960
    const int SMEM2 = 2 * (128 + 64) * RS_BYTES + 3072;        // 64512
    cudaFuncSetAttribute(gemm1_mma,  cudaFuncAttributeMaxDynamicSharedMemorySize, SMEM1);
    cudaFuncSetAttribute(gemm23_mma, cudaFuncAttributeMaxDynamicSharedMemorySize, SMEM2);

    // 1) feat partials: (8, 4, 4) = 128 CTAs
    gemm1_mma<<<dim3(D_ / 64, B_ / 64, SPLITK), 256, SMEM1>>>(x, Wb);
    // 2) combine + bias
    combine_feat_kernel<<<(B_ * D_) / 256, 256>>>(bb);
    // 3) fused out-head + proxy softmax partials: (64, 2) = 128 CTAs
    gemm23_mma<<<dim3(64, B_ / 128), 256, SMEM2>>>(Wm, bm, proxies, y, out);
    // 4) combine partials + scalars
    final_kernel<<<1, 256>>>(out);
}

// round 7
// speedup vs baseline: 1.8876x; 1.0203x over previous
#include <cuda_runtime.h>
#include <cuda_bf16.h>
#include <math.h>
#include <stdint.h>

#define B_   256
#define IN_  1024
#define D_   512
#define P_   2048
#define SPLITK 4
#define NT_P  (P_ / 64)     // 32 proxy n-tiles per row

// ---------------- scratch (device globals; no allocations allowed) ---------
__device__ float g_xT[B_ * IN_];                  // tf32-rounded x
__device__ float g_WbT[D_ * IN_];                 // tf32-rounded Wb
__device__ float g_feat_part[SPLITK * B_ * D_];   // split-K partials for GEMM1
__device__ float g_featT[B_ * D_];                // tf32-rounded feat
__device__ float g_feat_n2[B_];                   // per-row ||feat||^2 (fp32)
__device__ float g_pmax[B_ * NT_P];               // per (row, n-tile) partial max
__device__ float g_psum[B_ * NT_P];               // per (row, n-tile) partial sumexp
__device__ float g_sy[B_];                        // s[b, y[b]]
__device__ float g_row_val[B_];                   // logp[b, y[b]]

// ==================== tf32 mma.sync helpers ================================
__device__ __forceinline__ void mma_tf32(float c[4], const uint32_t a[4], const uint32_t b[2]) {
    asm volatile("mma.sync.aligned.m16n8k8.row.col.f32.tf32.tf32.f32 "
        "{%0,%1,%2,%3}, {%4,%5,%6,%7}, {%8,%9}, {%0,%1,%2,%3};"
        : "+f"(c[0]), "+f"(c[1]), "+f"(c[2]), "+f"(c[3])
        : "r"(a[0]), "r"(a[1]), "r"(a[2]), "r"(a[3]), "r"(b[0]), "r"(b[1]));
}

__device__ __forceinline__ float to_tf32(float x) {
    uint32_t r;
    asm("cvt.rna.tf32.f32 %0, %1;" : "=r"(r) : "f"(x));
    return __uint_as_float(r);
}

// SMEM tile layout ("pair-interleaved"): per row of Kc=32 floats, pair index
// p = j*4 + t holds float2 {X[j*8+t], X[j*8+t+4]}. Row stride 160B: LDS.64
// fragment fetches are conflict-free (banks 8r+2t all distinct per phase).
#define RS_BYTES 160
#define RS_F2    20

template<int ROWS>
__device__ __forceinline__ void pack_load(const float* __restrict__ src, int ldk,
        int row0, int kt, int tid, float4* v0, float4* v1)
{
    constexpr int T = (ROWS * 4) / 256;
#pragma unroll
    for (int it = 0; it < T; it++) {
        int task = it * 256 + tid;
        int r = task >> 2, j = task & 3;
        const float* p = src + (size_t)(row0 + r) * ldk + kt + j * 8;
        v0[it] = *(const float4*)p;
        v1[it] = *(const float4*)(p + 4);
    }
}

// CVT: round to tf32 at store; SQ: accumulate fp32 sumsq of original values
template<int ROWS, bool CVT, bool SQ>
__device__ __forceinline__ void pack_store(char* __restrict__ buf, int tid,
        const float4* v0, const float4* v1, float* sq)
{
    constexpr int T = (ROWS * 4) / 256;
#pragma unroll
    for (int it = 0; it < T; it++) {
        int task = it * 256 + tid;
        int r = task >> 2, j = task & 3;
        float4 a = v0[it], b = v1[it];
        if (SQ)
            sq[it] += a.x * a.x + a.y * a.y + a.z * a.z + a.w * a.w
                    + b.x * b.x + b.y * b.y + b.z * b.z + b.w * b.w;
        float4 w0, w1;
        if (CVT) {
            w0 = make_float4(to_tf32(a.x), to_tf32(b.x), to_tf32(a.y), to_tf32(b.y));
            w1 = make_float4(to_tf32(a.z), to_tf32(b.z), to_tf32(a.w), to_tf32(b.w));
        } else {
            w0 = make_float4(a.x, b.x, a.y, b.y);
            w1 = make_float4(a.z, b.z, a.w, b.w);
        }
        float4* dst = (float4*)(buf + r * RS_BYTES + j * 32);
        dst[0] = w0;
        dst[1] = w1;
    }
}

template<int WN8>
__device__ __forceinline__ void chunk_mma(const float2* __restrict__ As,
        const float2* __restrict__ Bs, int wm32, int wnb, int g, int t,
        float acc[2][WN8][4])
{
#pragma unroll
    for (int j = 0; j < 4; j++) {
        uint32_t af[2][4];
#pragma unroll
        for (int i = 0; i < 2; i++) {
            float2 p0 = As[(wm32 + i * 16 + g) * RS_F2 + j * 4 + t];
            float2 p1 = As[(wm32 + i * 16 + 8 + g) * RS_F2 + j * 4 + t];
            af[i][0] = __float_as_uint(p0.x);
            af[i][1] = __float_as_uint(p1.x);
            af[i][2] = __float_as_uint(p0.y);
            af[i][3] = __float_as_uint(p1.y);
        }
        uint32_t bf[WN8][2];
#pragma unroll
        for (int nn = 0; nn < WN8; nn++) {
            float2 pb = Bs[(wnb + nn * 8 + g) * RS_F2 + j * 4 + t];
            bf[nn][0] = __float_as_uint(pb.x);
            bf[nn][1] = __float_as_uint(pb.y);
        }
#pragma unroll
        for (int i = 0; i < 2; i++)
#pragma unroll
            for (int nn = 0; nn < WN8; nn++)
                mma_tf32(acc[i][nn], af[i], bf[nn]);
    }
}

// ---------------- prep: round x and Wb to tf32 once ------------------------
__global__ void prep_round(const float* __restrict__ x, const float* __restrict__ Wb)
{
    int i = blockIdx.x * 256 + threadIdx.x;           // float4 index, 196608 total
    const float4* src;
    float4* dst;
    int j;
    if (i < (B_ * IN_) / 4) { src = (const float4*)x;  dst = (float4*)g_xT;  j = i; }
    else { src = (const float4*)Wb; dst = (float4*)g_WbT; j = i - (B_ * IN_) / 4; }
    float4 v = src[j];
    v.x = to_tf32(v.x); v.y = to_tf32(v.y); v.z = to_tf32(v.z); v.w = to_tf32(v.w);
    dst[j] = v;
}

// ---------------- GEMM1: split-K partials of xT @ WbT^T (64x64 tiles) ------
__global__ __launch_bounds__(256, 1)
void gemm1_mma()
{
    extern __shared__ __align__(16) char smem[];
    constexpr int TB = 64 * RS_BYTES;                 // 10240
    char* As[2] = { smem,          smem + 2 * TB };
    char* Bs[2] = { smem + TB,     smem + 3 * TB };

    const int tid = threadIdx.x, wid = tid >> 5, lane = tid & 31;
    const int g = lane >> 2, t = lane & 3;
    const int n0 = blockIdx.x * 64;
    const int m0 = blockIdx.y * 64;
    const int z  = blockIdx.z;
    const int kb = z * (IN_ / SPLITK);
    const int wm32 = (wid & 1) * 32, wnb = (wid >> 1) * 16;

    float acc[2][2][4] = {};
    float4 a0[1], a1[1], b0[1], b1[1];

    pack_load<64>(g_xT,  IN_, m0, kb, tid, a0, a1);
    pack_load<64>(g_WbT, IN_, n0, kb, tid, b0, b1);
    pack_store<64, false, false>(As[0], tid, a0, a1, nullptr);
    pack_store<64, false, false>(Bs[0], tid, b0, b1, nullptr);
    __syncthreads();
    constexpr int NCH = (IN_ / SPLITK) / 32;          // 8
    for (int c = 0; c < NCH; c++) {
        if (c + 1 < NCH) {
            pack_load<64>(g_xT,  IN_, m0, kb + (c + 1) * 32, tid, a0, a1);
            pack_load<64>(g_WbT, IN_, n0, kb + (c + 1) * 32, tid, b0, b1);
        }
        chunk_mma<2>((const float2*)As[c & 1], (const float2*)Bs[c & 1],
                     wm32, wnb, g, t, acc);
        if (c + 1 < NCH) {
            pack_store<64, false, false>(As[(c + 1) & 1], tid, a0, a1, nullptr);
            pack_store<64, false, false>(Bs[(c + 1) & 1], tid, b0, b1, nullptr);
            __syncthreads();
        }
    }

    float* dst = g_feat_part + (size_t)z * B_ * D_;
#pragma unroll
    for (int i = 0; i < 2; i++) {
        int m = m0 + wm32 + i * 16 + g;
#pragma unroll
        for (int nn = 0; nn < 2; nn++) {
            int n = n0 + wnb + nn * 8 + 2 * t;
            *(float2*)(dst + (size_t)m * D_ + n) =
                make_float2(acc[i][nn][0], acc[i][nn][1]);
            *(float2*)(dst + (size_t)(m + 8) * D_ + n) =
                make_float2(acc[i][nn][2], acc[i][nn][3]);
        }
    }
}

// ---------------- combine: split-K reduce + bias + round + row norm --------
// One warp per feat row: writes g_featT (tf32) and g_feat_n2 (fp32).
__global__ void combine_feat_kernel(const float* __restrict__ bb)
{
    const int row  = blockIdx.x * 8 + (threadIdx.x >> 5);
    const int lane = threadIdx.x & 31;
    const float4* bias4 = (const float4*)bb;
    float4* dst4 = (float4*)(g_featT + (size_t)row * D_);
    float sq = 0.f;
#pragma unroll
    for (int i = 0; i < 4; i++) {
        int c4 = lane + 32 * i;                        // float4 column index
        float4 s = bias4[c4];
#pragma unroll
        for (int z = 0; z < SPLITK; z++) {
            float4 p = *(const float4*)(g_feat_part + (size_t)z * B_ * D_
                                        + (size_t)row * D_ + c4 * 4);
            s.x += p.x; s.y += p.y; s.z += p.z; s.w += p.w;
        }
        sq += s.x * s.x + s.y * s.y + s.z * s.z + s.w * s.w;
        s.x = to_tf32(s.x); s.y = to_tf32(s.y); s.z = to_tf32(s.z); s.w = to_tf32(s.w);
        dst4[c4] = s;
    }
#pragma unroll
    for (int o = 16; o; o >>= 1) sq += __shfl_xor_sync(0xffffffffu, sq, o);
    if (lane == 0) g_feat_n2[row] = sq;
}

// ---------------- fused GEMM2 (out) + GEMM3 (softmax partials) -------------
// Tiles 128(m) x 64(n), K=512. grid (64, 2) = 128 CTAs.
__global__ __launch_bounds__(256, 1)
void gemm23_mma(const float* __restrict__ Wm, const float* __restrict__ bm,
                const float* __restrict__ proxies, const int* __restrict__ y,
                float* __restrict__ out)
{
    extern __shared__ __align__(16) char smem[];
    constexpr int TBA = 128 * RS_BYTES;               // 20480
    constexpr int TBB = 64 * RS_BYTES;                // 10240
    char* As[2] = { smem,                smem + TBA + TBB };
    char* Bs[2] = { smem + TBA,          smem + 2 * TBA + TBB };
    float* pn2s = (float*)(smem + 2 * (TBA + TBB));   // [64]
    float* pmx  = pn2s + 64;                          // [128][2]
    float* psm  = pmx + 256;                          // [128][2]

    const int tid = threadIdx.x, wid = tid >> 5, lane = tid & 31;
    const int g = lane >> 2, t = lane & 3;
    const int nt = blockIdx.x;                        // 0..63
    const bool isp = (nt >= 32);
    const int n0 = (nt & 31) * 64;
    const int m0 = blockIdx.y * 128;
    const float* Bmat = isp ? proxies : Wm;
    const int wm32 = (wid & 3) * 32, wnb = (wid >> 2) * 32;
    const int half = wid >> 2;

    float acc[2][4][4] = {};
    float4 a0[2], a1[2], b0[1], b1[1];
    float sqB[1] = {0.f};

    pack_load<128>(g_featT, D_, m0, 0, tid, a0, a1);
    pack_load<64>(Bmat,    D_, n0, 0, tid, b0, b1);
    pack_store<128, false, false>(As[0], tid, a0, a1, nullptr);
    pack_store<64, true, true>(Bs[0], tid, b0, b1, sqB);
    __syncthreads();
    constexpr int NCH = D_ / 32;                      // 16
    for (int c = 0; c < NCH; c++) {
        if (c + 1 < NCH) {
            pack_load<128>(g_featT, D_, m0, (c + 1) * 32, tid, a0, a1);
            pack_load<64>(Bmat,    D_, n0, (c + 1) * 32, tid, b0, b1);
        }
        chunk_mma<4>((const float2*)As[c & 1], (const float2*)Bs[c & 1],
                     wm32, wnb, g, t, acc);
        if (c + 1 < NCH) {
            pack_store<128, false, false>(As[(c + 1) & 1], tid, a0, a1, nullptr);
            pack_store<64, true, true>(Bs[(c + 1) & 1], tid, b0, b1, sqB);
            __syncthreads();
        }
    }

    // per-row B sumsq (fp32, full K): quad-shuffle reduce -> smem
    {
        float sb = sqB[0];
        sb += __shfl_xor_sync(0xffffffffu, sb, 1);
        sb += __shfl_xor_sync(0xffffffffu, sb, 2);
        if ((tid & 3) == 0) pn2s[tid >> 2] = sb;
    }
    __syncthreads();

    if (!isp) {
#pragma unroll
        for (int i = 0; i < 2; i++) {
            int m = m0 + wm32 + i * 16 + g;
#pragma unroll
            for (int nn = 0; nn < 4; nn++) {
                int n = n0 + wnb + nn * 8 + 2 * t;
                float bn0 = bm[n], bn1 = bm[n + 1];
                *(float2*)(out + (size_t)m * P_ + n) =
                    make_float2(acc[i][nn][0] + bn0, acc[i][nn][1] + bn1);
                *(float2*)(out + (size_t)(m + 8) * P_ + n) =
                    make_float2(acc[i][nn][2] + bn0, acc[i][nn][3] + bn1);
            }
        }
    } else {
        // proxy: s = 2*dot - fn2 - pn2 in regs -> per-row (max, sumexp) + y-pick
#pragma unroll
        for (int i = 0; i < 2; i++) {
            const int rA = wm32 + i * 16 + g;
            const int rB = rA + 8;
            const float fa = g_feat_n2[m0 + rA], fb = g_feat_n2[m0 + rB];
            const int ya = y[m0 + rA], yb = y[m0 + rB];
            float sA[8], sB[8];
#pragma unroll
            for (int nn = 0; nn < 4; nn++) {
                int nl = wnb + nn * 8 + 2 * t;
                float p0 = pn2s[nl], p1 = pn2s[nl + 1];
                sA[nn * 2 + 0] = 2.f * acc[i][nn][0] - fa - p0;
                sA[nn * 2 + 1] = 2.f * acc[i][nn][1] - fa - p1;
                sB[nn * 2 + 0] = 2.f * acc[i][nn][2] - fb - p0;
                sB[nn * 2 + 1] = 2.f * acc[i][nn][3] - fb - p1;
                int n = n0 + nl;
                if (n     == ya) g_sy[m0 + rA] = sA[nn * 2 + 0];
                if (n + 1 == ya) g_sy[m0 + rA] = sA[nn * 2 + 1];
                if (n     == yb) g_sy[m0 + rB] = sB[nn * 2 + 0];
                if (n + 1 == yb) g_sy[m0 + rB] = sB[nn * 2 + 1];
            }
            float mA = sA[0], mB = sB[0];
#pragma unroll
            for (int u = 1; u < 8; u++) { mA = fmaxf(mA, sA[u]); mB = fmaxf(mB, sB[u]); }
            float eA = 0.f, eB = 0.f;
#pragma unroll
            for (int u = 0; u < 8; u++) { eA += expf(sA[u] - mA); eB += expf(sB[u] - mB); }
#pragma unroll
            for (int o = 1; o <= 2; o <<= 1) {
                float mA2 = __shfl_xor_sync(0xffffffffu, mA, o);
                float eA2 = __shfl_xor_sync(0xffffffffu, eA, o);
                float mB2 = __shfl_xor_sync(0xffffffffu, mB, o);
                float eB2 = __shfl_xor_sync(0xffffffffu, eB, o);
                float M = fmaxf(mA, mA2);
                eA = eA * expf(mA - M) + eA2 * expf(mA2 - M); mA = M;
                M = fmaxf(mB, mB2);
                eB = eB * expf(mB - M) + eB2 * expf(mB2 - M); mB = M;
            }
            if (t == 0) {
                pmx[rA * 2 + half] = mA; psm[rA * 2 + half] = eA;
                pmx[rB * 2 + half] = mB; psm[rB * 2 + half] = eB;
            }
        }
        __syncthreads();
        if (tid < 128) {
            float m1 = pmx[tid * 2], m2 = pmx[tid * 2 + 1];
            float M = fmaxf(m1, m2);
            float S = psm[tid * 2] * expf(m1 - M) + psm[tid * 2 + 1] * expf(m2 - M);
            int idx = (m0 + tid) * NT_P + (nt - 32);
            g_pmax[idx] = M;
            g_psum[idx] = S;
        }
    }
}

// ---------------- logsumexp combine across n-tiles (8 threads/row) ---------
__global__ void loss_combine_kernel()
{
    const int tid = threadIdx.x;
    const int b = blockIdx.x * 32 + (tid >> 3);       // 8 blocks x 32 rows
    const int t = tid & 7;
    const float4 m4 = ((const float4*)(g_pmax + b * NT_P))[t];
    const float4 s4 = ((const float4*)(g_psum + b * NT_P))[t];
    float M = fmaxf(fmaxf(m4.x, m4.y), fmaxf(m4.z, m4.w));
    float S = s4.x * expf(m4.x - M) + s4.y * expf(m4.y - M)
            + s4.z * expf(m4.z - M) + s4.w * expf(m4.w - M);
#pragma unroll
    for (int o = 1; o <= 4; o <<= 1) {
        float M2 = __shfl_xor_sync(0xffffffffu, M, o);
        float S2 = __shfl_xor_sync(0xffffffffu, S, o);
        float Mn = fmaxf(M, M2);
        S = S * expf(M - Mn) + S2 * expf(M2 - Mn);
        M = Mn;
    }
    if (t == 0) g_row_val[b] = g_sy[b] - M - logf(S);
}

// ---------------- final scalars --------------------------------------------
__global__ void final_kernel(float* __restrict__ out)
{
    __shared__ float r1[256], r2[256];
    const int b = threadIdx.x;
    r1[b] = g_row_val[b];
    r2[b] = sqrtf(g_feat_n2[b]);
    __syncthreads();
    for (int st = 128; st > 0; st >>= 1) {
        if (b < st) { r1[b] += r1[b + st]; r2[b] += r2[b + st]; }
        __syncthreads();
    }
    if (b == 0) {
        out[(size_t)B_ * P_]     = -r1[0] / (float)B_;  // loss
        out[(size_t)B_ * P_ + 1] =  r2[0] / (float)B_;  // reg_e
    }
}

// ---------------- launch ----------------------------------------------------
extern "C" void kernel_launch(void* const* d_in, const int* in_sizes, int n_in,
                              void* d_out, int out_size)
{
    const float* x       = (const float*)d_in[0];
    const int*   y       = (const int*)  d_in[1];
    const float* Wb      = (const float*)d_in[2];
    const float* bb      = (const float*)d_in[3];
    const float* Wm      = (const float*)d_in[4];
    const float* bm      = (const float*)d_in[5];
    const float* proxies = (const float*)d_in[6];
    float* out = (float*)d_out;

    const int SMEM1 = 4 * 64 * RS_BYTES;                       // 40960
    const int SMEM2 = 2 * (128 + 64) * RS_BYTES + 3072;        // 64512
    cudaFuncSetAttribute(gemm1_mma,  cudaFuncAttributeMaxDynamicSharedMemorySize, SMEM1);
    cudaFuncSetAttribute(gemm23_mma, cudaFuncAttributeMaxDynamicSharedMemorySize, SMEM2);

    // 0) round x, Wb to tf32 once
    prep_round<<<((B_ + D_) * IN_ / 4) / 256, 256>>>(x, Wb);
    // 1) feat partials: (8, 4, 4) = 128 CTAs
    gemm1_mma<<<dim3(D_ / 64, B_ / 64, SPLITK), 256, SMEM1>>>();
    // 2) combine + bias + round + row norms (warp per row)
    combine_feat_kernel<<<B_ / 8, 256>>>(bb);
    // 3) fused out-head + proxy softmax partials: (64, 2) = 128 CTAs
    gemm23_mma<<<dim3(64, B_ / 128), 256, SMEM2>>>(Wm, bm, proxies, y, out);
    // 4) logsumexp combine (8 blocks)
    loss_combine_kernel<<<8, 256>>>();
    // 5) scalars
    final_kernel<<<1, 256>>>(out);
}

// round 8
// speedup vs baseline: 2.0873x; 1.1058x over previous
#include <cuda_runtime.h>
#include <cuda_bf16.h>
#include <math.h>
#include <stdint.h>

#define B_   256
#define IN_  1024
#define D_   512
#define P_   2048
#define SPLITK 4
#define NT_P  (P_ / 64)     // 32 proxy n-tiles per row

// ---------------- scratch (device globals; no allocations allowed) ---------
__device__ float g_feat_part[SPLITK * B_ * D_];   // split-K partials for GEMM1
__device__ float g_featT[B_ * D_];                // tf32-rounded feat
__device__ float g_feat_n2[B_];                   // per-row ||feat||^2 (fp32)
__device__ float g_pmax[B_ * NT_P];               // per (row, n-tile) partial max
__device__ float g_psum[B_ * NT_P];               // per (row, n-tile) partial sumexp
__device__ float g_sy[B_];                        // s[b, y[b]]
__device__ float g_row_val[B_];                   // logp[b, y[b]]

// ==================== tf32 mma.sync helpers ================================
__device__ __forceinline__ void mma_tf32(float c[4], const uint32_t a[4], const uint32_t b[2]) {
    asm volatile("mma.sync.aligned.m16n8k8.row.col.f32.tf32.tf32.f32 "
        "{%0,%1,%2,%3}, {%4,%5,%6,%7}, {%8,%9}, {%0,%1,%2,%3};"
        : "+f"(c[0]), "+f"(c[1]), "+f"(c[2]), "+f"(c[3])
        : "r"(a[0]), "r"(a[1]), "r"(a[2]), "r"(a[3]), "r"(b[0]), "r"(b[1]));
}

__device__ __forceinline__ float to_tf32(float x) {
    uint32_t r;
    asm("cvt.rna.tf32.f32 %0, %1;" : "=r"(r) : "f"(x));
    return __uint_as_float(r);
}
__device__ __forceinline__ uint32_t fu(float x) { return __float_as_uint(x); }

// SMEM layout per tile row (Kc=32 floats): float4 at word offset t*8 + jj*4
// holds {X[jj*16+t], X[jj*16+4+t], X[jj*16+8+t], X[jj*16+12+t]} — i.e. the two
// k-pairs a thread (k-lane t) needs for mma j = 2jj and 2jj+1, in one LDS.128.
// Row stride 44 words (176B): fragment-read banks = g*12 + t*8 mod 32, all
// distinct within every 8-lane phase -> conflict-free LDS.128.
#define RS_W 44

// one Kc=32 chunk of warp mma: warp tile (WM16*16) x (WN8*8)
template<int WM16, int WN8>
__device__ __forceinline__ void chunk_mma(const float* __restrict__ As,
        const float* __restrict__ Bs, int wm, int wn, int g, int t,
        float acc[WM16][WN8][4])
{
#pragma unroll
    for (int jj = 0; jj < 2; jj++) {
        float4 qa[WM16][2];
        float4 qb[WN8];
#pragma unroll
        for (int i = 0; i < WM16; i++) {
            qa[i][0] = *(const float4*)(As + (wm + i * 16 + g) * RS_W + t * 8 + jj * 4);
            qa[i][1] = *(const float4*)(As + (wm + i * 16 + 8 + g) * RS_W + t * 8 + jj * 4);
        }
#pragma unroll
        for (int nn = 0; nn < WN8; nn++)
            qb[nn] = *(const float4*)(Bs + (wn + nn * 8 + g) * RS_W + t * 8 + jj * 4);
#pragma unroll
        for (int i = 0; i < WM16; i++) {
            uint32_t a0[4] = { fu(qa[i][0].x), fu(qa[i][1].x), fu(qa[i][0].y), fu(qa[i][1].y) };
            uint32_t a1[4] = { fu(qa[i][0].z), fu(qa[i][1].z), fu(qa[i][0].w), fu(qa[i][1].w) };
#pragma unroll
            for (int nn = 0; nn < WN8; nn++) {
                uint32_t b0[2] = { fu(qb[nn].x), fu(qb[nn].y) };
                uint32_t b1[2] = { fu(qb[nn].z), fu(qb[nn].w) };
                mma_tf32(acc[i][nn], a0, b0);
                mma_tf32(acc[i][nn], a1, b1);
            }
        }
    }
}

// ---------------- GEMM1: split-K partials of x @ Wb^T (64x64, 512 thr) -----
__global__ __launch_bounds__(512, 1)
void gemm1_mma(const float* __restrict__ x, const float* __restrict__ Wb)
{
    extern __shared__ __align__(16) float smem[];
    constexpr int TW = 64 * RS_W;               // floats per tile
    constexpr int STG = 2 * TW;                 // stage = A tile + B tile

    const int tid = threadIdx.x, wid = tid >> 5, lane = tid & 31;
    const int g = lane >> 2, t = lane & 3;
    const int n0 = blockIdx.x * 64, m0 = blockIdx.y * 64;
    const int kb = blockIdx.z * (IN_ / SPLITK);
    const int wm = (wid & 3) * 16, wn = (wid >> 2) * 16;

    const bool isA = tid < 128, act = tid < 256;
    const int task = isA ? tid : tid - 128;
    const int r = task >> 1, jj = task & 1;
    const float* src = isA ? (x + (size_t)(m0 + r) * IN_) : (Wb + (size_t)(n0 + r) * IN_);
    const int seg = isA ? 0 : TW;

    float acc[1][2][4] = {};
    float4 v[4];

    auto ld = [&](int c) {
        if (act) {
            const float4* p = (const float4*)(src + kb + c * 32 + jj * 16);
            v[0] = p[0]; v[1] = p[1]; v[2] = p[2]; v[3] = p[3];
        }
    };
    auto st = [&](int c) {
        if (act) {
            float a0[4] = {v[0].x, v[0].y, v[0].z, v[0].w};
            float a1[4] = {v[1].x, v[1].y, v[1].z, v[1].w};
            float a2[4] = {v[2].x, v[2].y, v[2].z, v[2].w};
            float a3[4] = {v[3].x, v[3].y, v[3].z, v[3].w};
            float* dst = smem + (c & 1) * STG + seg + r * RS_W + jj * 4;
#pragma unroll
            for (int tt = 0; tt < 4; tt++)
                *(float4*)(dst + tt * 8) = make_float4(to_tf32(a0[tt]), to_tf32(a1[tt]),
                                                       to_tf32(a2[tt]), to_tf32(a3[tt]));
        }
    };

    ld(0); st(0); __syncthreads();
    constexpr int NCH = (IN_ / SPLITK) / 32;    // 8
    for (int c = 0; c < NCH; c++) {
        if (c + 1 < NCH) ld(c + 1);
        const float* stg = smem + (c & 1) * STG;
        chunk_mma<1, 2>(stg, stg + TW, wm, wn, g, t, acc);
        if (c + 1 < NCH) { st(c + 1); __syncthreads(); }
    }

    float* dst = g_feat_part + (size_t)blockIdx.z * B_ * D_;
    const int m = m0 + wm + g;
#pragma unroll
    for (int nn = 0; nn < 2; nn++) {
        int n = n0 + wn + nn * 8 + 2 * t;
        *(float2*)(dst + (size_t)m * D_ + n)       = make_float2(acc[0][nn][0], acc[0][nn][1]);
        *(float2*)(dst + (size_t)(m + 8) * D_ + n) = make_float2(acc[0][nn][2], acc[0][nn][3]);
    }
}

// ---------------- combine: split-K reduce + bias + round + row norm --------
__global__ void combine_feat_kernel(const float* __restrict__ bb)
{
    const int row  = blockIdx.x * 8 + (threadIdx.x >> 5);
    const int lane = threadIdx.x & 31;
    const float4* bias4 = (const float4*)bb;
    float4* dst4 = (float4*)(g_featT + (size_t)row * D_);
    float sq = 0.f;
#pragma unroll
    for (int i = 0; i < 4; i++) {
        int c4 = lane + 32 * i;
        float4 s = bias4[c4];
#pragma unroll
        for (int z = 0; z < SPLITK; z++) {
            float4 p = *(const float4*)(g_feat_part + (size_t)z * B_ * D_
                                        + (size_t)row * D_ + c4 * 4);
            s.x += p.x; s.y += p.y; s.z += p.z; s.w += p.w;
        }
        sq += s.x * s.x + s.y * s.y + s.z * s.z + s.w * s.w;
        s.x = to_tf32(s.x); s.y = to_tf32(s.y); s.z = to_tf32(s.z); s.w = to_tf32(s.w);
        dst4[c4] = s;
    }
#pragma unroll
    for (int o = 16; o; o >>= 1) sq += __shfl_xor_sync(0xffffffffu, sq, o);
    if (lane == 0) g_feat_n2[row] = sq;
}

// ---------------- fused GEMM2 (out) + GEMM3 (softmax partials), 512 thr ----
// Tile 128(m) x 64(n), K=512. grid (64, 2) = 128 CTAs, 16 warps each.
__global__ __launch_bounds__(512, 1)
void gemm23_mma(const float* __restrict__ Wm, const float* __restrict__ bm,
                const float* __restrict__ proxies, const int* __restrict__ y,
                float* __restrict__ out)
{
    extern __shared__ __align__(16) float smem[];
    constexpr int TAW = 128 * RS_W;             // 5632 floats
    constexpr int TBW = 64 * RS_W;              // 2816
    constexpr int STG = TAW + TBW;
    float* pn2s = smem + 2 * STG;               // [64]
    float* pmx  = pn2s + 64;                    // [128][4]
    float* psm  = pmx + 512;                    // [128][4]

    const int tid = threadIdx.x, wid = tid >> 5, lane = tid & 31;
    const int g = lane >> 2, t = lane & 3;
    const int nt = blockIdx.x;                  // 0..63
    const bool isp = (nt >= 32);
    const int n0 = (nt & 31) * 64;
    const int m0 = blockIdx.y * 128;
    const float* Bmat = isp ? proxies : Wm;
    const int wm = (wid & 3) * 32, wn = (wid >> 2) * 16, wc = wid >> 2;

    const bool isA = tid < 256, act = tid < 384;
    const int task = isA ? tid : tid - 256;
    const int r = task >> 1, jj = task & 1;
    const float* src = isA ? (g_featT + (size_t)(m0 + r) * D_)
                           : (Bmat + (size_t)(n0 + r) * D_);
    const int seg = isA ? 0 : TAW;

    float acc[2][2][4] = {};
    float4 v[4];
    float sq = 0.f;

    auto ld = [&](int c) {
        if (act) {
            const float4* p = (const float4*)(src + c * 32 + jj * 16);
            v[0] = p[0]; v[1] = p[1]; v[2] = p[2]; v[3] = p[3];
        }
    };
    auto st = [&](int c) {
        if (act) {
            float a0[4] = {v[0].x, v[0].y, v[0].z, v[0].w};
            float a1[4] = {v[1].x, v[1].y, v[1].z, v[1].w};
            float a2[4] = {v[2].x, v[2].y, v[2].z, v[2].w};
            float a3[4] = {v[3].x, v[3].y, v[3].z, v[3].w};
            float* dst = smem + (c & 1) * STG + seg + r * RS_W + jj * 4;
            if (isA) {      // feat already tf32-rounded
#pragma unroll
                for (int tt = 0; tt < 4; tt++)
                    *(float4*)(dst + tt * 8) = make_float4(a0[tt], a1[tt], a2[tt], a3[tt]);
            } else {        // B side: fp32 sumsq + round
#pragma unroll
                for (int u = 0; u < 4; u++)
                    sq += a0[u] * a0[u] + a1[u] * a1[u] + a2[u] * a2[u] + a3[u] * a3[u];
#pragma unroll
                for (int tt = 0; tt < 4; tt++)
                    *(float4*)(dst + tt * 8) = make_float4(to_tf32(a0[tt]), to_tf32(a1[tt]),
                                                           to_tf32(a2[tt]), to_tf32(a3[tt]));
            }
        }
    };

    ld(0); st(0); __syncthreads();
    constexpr int NCH = D_ / 32;                // 16
    for (int c = 0; c < NCH; c++) {
        if (c + 1 < NCH) ld(c + 1);
        const float* stg = smem + (c & 1) * STG;
        chunk_mma<2, 2>(stg, stg + TAW, wm, wn, g, t, acc);
        if (c + 1 < NCH) { st(c + 1); __syncthreads(); }
    }

    // B-row sumsq: tasks (r,0),(r,1) sit on adjacent lanes -> pair shuffle
    {
        float sb = sq + __shfl_xor_sync(0xffffffffu, sq, 1);
        if (act && !isA && (lane & 1) == 0) pn2s[(tid - 256) >> 1] = sb;
    }
    __syncthreads();

    if (!isp) {
#pragma unroll
        for (int i = 0; i < 2; i++) {
            int m = m0 + wm + i * 16 + g;
#pragma unroll
            for (int nn = 0; nn < 2; nn++) {
                int n = n0 + wn + nn * 8 + 2 * t;
                float bn0 = bm[n], bn1 = bm[n + 1];
                *(float2*)(out + (size_t)m * P_ + n) =
                    make_float2(acc[i][nn][0] + bn0, acc[i][nn][1] + bn1);
                *(float2*)(out + (size_t)(m + 8) * P_ + n) =
                    make_float2(acc[i][nn][2] + bn0, acc[i][nn][3] + bn1);
            }
        }
    } else {
        // proxy: s = 2*dot - fn2 - pn2 in regs -> per-(row, warp) (max, sumexp)
#pragma unroll
        for (int i = 0; i < 2; i++) {
            const int rA = wm + i * 16 + g;
            const int rB = rA + 8;
            const float fa = g_feat_n2[m0 + rA], fb = g_feat_n2[m0 + rB];
            const int ya = y[m0 + rA], yb = y[m0 + rB];
            float sA[4], sB[4];
#pragma unroll
            for (int nn = 0; nn < 2; nn++) {
                int nl = wn + nn * 8 + 2 * t;
                float p0 = pn2s[nl], p1 = pn2s[nl + 1];
                sA[nn * 2 + 0] = 2.f * acc[i][nn][0] - fa - p0;
                sA[nn * 2 + 1] = 2.f * acc[i][nn][1] - fa - p1;
                sB[nn * 2 + 0] = 2.f * acc[i][nn][2] - fb - p0;
                sB[nn * 2 + 1] = 2.f * acc[i][nn][3] - fb - p1;
                int n = n0 + nl;
                if (n     == ya) g_sy[m0 + rA] = sA[nn * 2 + 0];
                if (n + 1 == ya) g_sy[m0 + rA] = sA[nn * 2 + 1];
                if (n     == yb) g_sy[m0 + rB] = sB[nn * 2 + 0];
                if (n + 1 == yb) g_sy[m0 + rB] = sB[nn * 2 + 1];
            }
            float mA = fmaxf(fmaxf(sA[0], sA[1]), fmaxf(sA[2], sA[3]));
            float mB = fmaxf(fmaxf(sB[0], sB[1]), fmaxf(sB[2], sB[3]));
            float eA = expf(sA[0] - mA) + expf(sA[1] - mA)
                     + expf(sA[2] - mA) + expf(sA[3] - mA);
            float eB = expf(sB[0] - mB) + expf(sB[1] - mB)
                     + expf(sB[2] - mB) + expf(sB[3] - mB);
#pragma unroll
            for (int o = 1; o <= 2; o <<= 1) {
                float mA2 = __shfl_xor_sync(0xffffffffu, mA, o);
                float eA2 = __shfl_xor_sync(0xffffffffu, eA, o);
                float mB2 = __shfl_xor_sync(0xffffffffu, mB, o);
                float eB2 = __shfl_xor_sync(0xffffffffu, eB, o);
                float M = fmaxf(mA, mA2);
                eA = eA * expf(mA - M) + eA2 * expf(mA2 - M); mA = M;
                M = fmaxf(mB, mB2);
                eB = eB * expf(mB - M) + eB2 * expf(mB2 - M); mB = M;
            }
            if (t == 0) {
                pmx[rA * 4 + wc] = mA; psm[rA * 4 + wc] = eA;
                pmx[rB * 4 + wc] = mB; psm[rB * 4 + wc] = eB;
            }
        }
        __syncthreads();
        if (tid < 128) {
            float4 m4 = *(const float4*)(pmx + tid * 4);
            float4 s4 = *(const float4*)(psm + tid * 4);
            float M = fmaxf(fmaxf(m4.x, m4.y), fmaxf(m4.z, m4.w));
            float S = s4.x * expf(m4.x - M) + s4.y * expf(m4.y - M)
                    + s4.z * expf(m4.z - M) + s4.w * expf(m4.w - M);
            int idx = (m0 + tid) * NT_P + (nt - 32);
            g_pmax[idx] = M;
            g_psum[idx] = S;
        }
    }
}

// ---------------- logsumexp combine across n-tiles (8 threads/row) ---------
__global__ void loss_combine_kernel()
{
    const int tid = threadIdx.x;
    const int b = blockIdx.x * 32 + (tid >> 3);
    const int t = tid & 7;
    const float4 m4 = ((const float4*)(g_pmax + b * NT_P))[t];
    const float4 s4 = ((const float4*)(g_psum + b * NT_P))[t];
    float M = fmaxf(fmaxf(m4.x, m4.y), fmaxf(m4.z, m4.w));
    float S = s4.x * expf(m4.x - M) + s4.y * expf(m4.y - M)
            + s4.z * expf(m4.z - M) + s4.w * expf(m4.w - M);
#pragma unroll
    for (int o = 1; o <= 4; o <<= 1) {
        float M2 = __shfl_xor_sync(0xffffffffu, M, o);
        float S2 = __shfl_xor_sync(0xffffffffu, S, o);
        float Mn = fmaxf(M, M2);
        S = S * expf(M - Mn) + S2 * expf(M2 - Mn);
        M = Mn;
    }
    if (t == 0) g_row_val[b] = g_sy[b] - M - logf(S);
}

// ---------------- final scalars --------------------------------------------
__global__ void final_kernel(float* __restrict__ out)
{
    __shared__ float r1[256], r2[256];
    const int b = threadIdx.x;
    r1[b] = g_row_val[b];
    r2[b] = sqrtf(g_feat_n2[b]);
    __syncthreads();
    for (int st = 128; st > 0; st >>= 1) {
        if (b < st) { r1[b] += r1[b + st]; r2[b] += r2[b + st]; }
        __syncthreads();
    }
    if (b == 0) {
        out[(size_t)B_ * P_]     = -r1[0] / (float)B_;  // loss
        out[(size_t)B_ * P_ + 1] =  r2[0] / (float)B_;  // reg_e
    }
}

// ---------------- launch ----------------------------------------------------
extern "C" void kernel_launch(void* const* d_in, const int* in_sizes, int n_in,
                              void* d_out, int out_size)
{
    const float* x       = (const float*)d_in[0];
    const int*   y       = (const int*)  d_in[1];
    const float* Wb      = (const float*)d_in[2];
    const float* bb      = (const float*)d_in[3];
    const float* Wm      = (const float*)d_in[4];
    const float* bm      = (const float*)d_in[5];
    const float* proxies = (const float*)d_in[6];
    float* out = (float*)d_out;

    const int SMEM1 = 4 * 64 * RS_W * 4;                        // 45056 B
    const int SMEM2 = (2 * (128 + 64) * RS_W + 64 + 1024) * 4;  // 71936 B
    cudaFuncSetAttribute(gemm1_mma,  cudaFuncAttributeMaxDynamicSharedMemorySize, SMEM1);
    cudaFuncSetAttribute(gemm23_mma, cudaFuncAttributeMaxDynamicSharedMemorySize, SMEM2);

    // 1) feat partials: (8, 4, 4) = 128 CTAs, 512 thr
    gemm1_mma<<<dim3(D_ / 64, B_ / 64, SPLITK), 512, SMEM1>>>(x, Wb);
    // 2) combine + bias + round + row norms
    combine_feat_kernel<<<B_ / 8, 256>>>(bb);
    // 3) fused out-head + proxy softmax partials: (64, 2) = 128 CTAs, 512 thr
    gemm23_mma<<<dim3(64, B_ / 128), 512, SMEM2>>>(Wm, bm, proxies, y, out);
    // 4) logsumexp combine
    loss_combine_kernel<<<8, 256>>>();
    // 5) scalars
    final_kernel<<<1, 256>>>(out);
}